// round 1
// baseline (speedup 1.0000x reference)
#include <cuda_runtime.h>

#define XDIM 128
#define X3   (XDIM * XDIM * XDIM)   // 2,097,152 voxels
#define NB   16                     // batch

// Scratch: grid stored batch-minor: g_grid[v*NB + b]  (128 MiB, zero-init at load,
// re-zeroed by memset each launch). Accumulators in double for deterministic-enough
// final fp32 cast.
__device__ float  g_grid[(size_t)X3 * NB];
__device__ double g_acc[2 * NB];   // [0..15] tv sums, [16..31] mse sums

// ---------------------------------------------------------------------------
// Scatter: one thread per index n; 16 atomics land in 64 contiguous bytes.
// ---------------------------------------------------------------------------
__global__ void scatter_kernel(const int* __restrict__ idx,
                               const float* __restrict__ vals, int N) {
    int n = blockIdx.x * blockDim.x + threadIdx.x;
    if (n >= N) return;
    int z = idx[3 * n + 0];
    int y = idx[3 * n + 1];
    int x = idx[3 * n + 2];
    int v = (z * XDIM + y) * XDIM + x;
    float* base = g_grid + (size_t)v * NB;
#pragma unroll
    for (int b = 0; b < NB; b++) {
        // vals[b*N + n]: coalesced across threads for each b
        atomicAdd(base + b, vals[(size_t)b * N + n]);
    }
}

// ---------------------------------------------------------------------------
// Reduce: work item w = (voxel v, batch-group bg of 4). float4 loads of self and
// x+1 / y+1 / z+1 neighbors; forward diffs -> |d| and d^2 accumulation.
// Thread's bg is fixed (total threads multiple of 4), so per-thread float[4]
// accumulators map to batches bg*4 + c.
// ---------------------------------------------------------------------------
__global__ void reduce_kernel() {
    const float4* __restrict__ g4 = (const float4*)g_grid;
    int tid = blockIdx.x * blockDim.x + threadIdx.x;
    int T   = gridDim.x * blockDim.x;          // multiple of 4
    int bg  = tid & 3;

    float tv[4]  = {0.f, 0.f, 0.f, 0.f};
    float mse[4] = {0.f, 0.f, 0.f, 0.f};

    const int W = X3 * 4;
    for (int w = tid; w < W; w += T) {
        int v = w >> 2;
        int x = v & (XDIM - 1);
        int y = (v >> 7) & (XDIM - 1);
        int z = v >> 14;
        int base = (v << 2) + bg;              // float4 index: v*4 + bg

        float4 s = g4[base];

        if (x < XDIM - 1) {
            float4 n = g4[base + 4];
            float dx = n.x - s.x, dy = n.y - s.y, dz = n.z - s.z, dw = n.w - s.w;
            tv[0] += fabsf(dx); tv[1] += fabsf(dy); tv[2] += fabsf(dz); tv[3] += fabsf(dw);
            mse[0] += dx * dx;  mse[1] += dy * dy;  mse[2] += dz * dz;  mse[3] += dw * dw;
        }
        if (y < XDIM - 1) {
            float4 n = g4[base + 4 * XDIM];
            float dx = n.x - s.x, dy = n.y - s.y, dz = n.z - s.z, dw = n.w - s.w;
            tv[0] += fabsf(dx); tv[1] += fabsf(dy); tv[2] += fabsf(dz); tv[3] += fabsf(dw);
            mse[0] += dx * dx;  mse[1] += dy * dy;  mse[2] += dz * dz;  mse[3] += dw * dw;
        }
        if (z < XDIM - 1) {
            float4 n = g4[base + 4 * XDIM * XDIM];
            float dx = n.x - s.x, dy = n.y - s.y, dz = n.z - s.z, dw = n.w - s.w;
            tv[0] += fabsf(dx); tv[1] += fabsf(dy); tv[2] += fabsf(dz); tv[3] += fabsf(dw);
            mse[0] += dx * dx;  mse[1] += dy * dy;  mse[2] += dz * dz;  mse[3] += dw * dw;
        }
    }

    // Warp reduce over the 8 lanes that share bg (xor over lane bits 4,3,2).
#pragma unroll
    for (int off = 16; off >= 4; off >>= 1) {
#pragma unroll
        for (int c = 0; c < 4; c++) {
            tv[c]  += __shfl_xor_sync(0xffffffffu, tv[c],  off);
            mse[c] += __shfl_xor_sync(0xffffffffu, mse[c], off);
        }
    }

    // Block partials in shared (indexed by batch), then one set of double atomics.
    __shared__ float s_tv[NB], s_mse[NB];
    if (threadIdx.x < NB) { s_tv[threadIdx.x] = 0.f; s_mse[threadIdx.x] = 0.f; }
    __syncthreads();

    int lane = threadIdx.x & 31;
    if (lane < 4) {                 // lane == bg for these lanes
#pragma unroll
        for (int c = 0; c < 4; c++) {
            atomicAdd(&s_tv[bg * 4 + c],  tv[c]);
            atomicAdd(&s_mse[bg * 4 + c], mse[c]);
        }
    }
    __syncthreads();

    if (threadIdx.x < NB) {
        atomicAdd(&g_acc[threadIdx.x],      (double)s_tv[threadIdx.x]);
        atomicAdd(&g_acc[NB + threadIdx.x], (double)s_mse[threadIdx.x]);
    }
}

// ---------------------------------------------------------------------------
// Finalize: normalize and emit [2, B] floats.
// ---------------------------------------------------------------------------
__global__ void finalize_kernel(float* __restrict__ out) {
    int t = threadIdx.x;            // 0..31
    double norm = (t < NB) ? (double)X3 : (double)(2 * XDIM * XDIM - 2 * XDIM);
    out[t] = (float)(g_acc[t] / norm);
}

extern "C" void kernel_launch(void* const* d_in, const int* in_sizes, int n_in,
                              void* d_out, int out_size) {
    const int*   indices = (const int*)d_in[0];
    const float* values  = (const float*)d_in[1];
    int N = in_sizes[0] / 3;        // 500000

    void* gptr = nullptr;
    void* aptr = nullptr;
    cudaGetSymbolAddress(&gptr, g_grid);
    cudaGetSymbolAddress(&aptr, g_acc);

    // Zero grid + accumulators (graph-capturable memset nodes).
    cudaMemsetAsync(gptr, 0, sizeof(float) * (size_t)X3 * NB);
    cudaMemsetAsync(aptr, 0, sizeof(double) * 2 * NB);

    scatter_kernel<<<(N + 255) / 256, 256>>>(indices, values, N);
    reduce_kernel<<<2048, 256>>>();
    finalize_kernel<<<1, 32>>>((float*)d_out);
}

// round 2
// speedup vs baseline: 1.7343x; 1.7343x over previous
#include <cuda_runtime.h>

#define XDIM 128
#define X3   (XDIM * XDIM * XDIM)   // 2,097,152 voxels
#define NB   16                     // batch

// Grid stored batch-minor: g_grid[v*NB + b]. Zero-initialized at module load.
// INVARIANT: grid is all-zero at entry to every kernel_launch. Maintained by
// zero_touched_kernel (re-zeroes every voxel scatter wrote) and finalize
// (re-zeroes g_acc after reading).
__device__ float  g_grid[(size_t)X3 * NB];
__device__ double g_acc[2 * NB];   // [0..15] tv sums, [16..31] mse sums

// ---------------------------------------------------------------------------
// Scatter: one thread per index n; 4 vector red.v4.f32 (64B) per index.
// ---------------------------------------------------------------------------
__global__ void scatter_kernel(const int* __restrict__ idx,
                               const float* __restrict__ vals, int N) {
    int n = blockIdx.x * blockDim.x + threadIdx.x;
    if (n >= N) return;
    int z = idx[3 * n + 0];
    int y = idx[3 * n + 1];
    int x = idx[3 * n + 2];
    size_t base = (size_t)((z * XDIM + y) * XDIM + x) * NB;

    float v[NB];
#pragma unroll
    for (int b = 0; b < NB; b++) v[b] = vals[(size_t)b * N + n];

#pragma unroll
    for (int g = 0; g < 4; g++) {
        float* p = g_grid + base + g * 4;
        asm volatile("red.global.add.v4.f32 [%0], {%1, %2, %3, %4};"
                     :: "l"(p), "f"(v[g * 4 + 0]), "f"(v[g * 4 + 1]),
                        "f"(v[g * 4 + 2]), "f"(v[g * 4 + 3])
                     : "memory");
    }
}

// ---------------------------------------------------------------------------
// Zero only the voxels scatter touched (duplicates harmlessly re-zero).
// ---------------------------------------------------------------------------
__global__ void zero_touched_kernel(const int* __restrict__ idx, int N) {
    int n = blockIdx.x * blockDim.x + threadIdx.x;
    if (n >= N) return;
    int z = idx[3 * n + 0];
    int y = idx[3 * n + 1];
    int x = idx[3 * n + 2];
    float4* p = (float4*)(g_grid + (size_t)((z * XDIM + y) * XDIM + x) * NB);
    float4 z4 = make_float4(0.f, 0.f, 0.f, 0.f);
    p[0] = z4; p[1] = z4; p[2] = z4; p[3] = z4;
}

// ---------------------------------------------------------------------------
// Reduce: block = (4 z) x (16 y) x (4 bg) = 256 threads. Each thread walks a
// half x-row carrying the previous voxel in a register (x-diff is free).
// y+1 loads L1-hit (same warp's self lines); z+1 loads L1-hit for 3/4 planes
// (neighbor plane self-loaded by same block).
// ---------------------------------------------------------------------------
__global__ void reduce_kernel() {
    const float4* __restrict__ g4 = (const float4*)g_grid;
    int tid = threadIdx.x;
    int bg = tid & 3;
    int yl = (tid >> 2) & 15;
    int zl = tid >> 6;                       // 0..3
    int xh = blockIdx.x;                     // 0..1  (x half)
    int y  = blockIdx.y * 16 + yl;           // 0..127
    int z  = blockIdx.z * 4 + zl;            // 0..127

    size_t rowbase = (size_t)((z * XDIM + y) * XDIM) * 4 + bg;  // float4 idx at x=0
    const bool yok = (y < XDIM - 1);
    const bool zok = (z < XDIM - 1);

    float tv0 = 0.f, tv1 = 0.f, tv2 = 0.f, tv3 = 0.f;
    float ms0 = 0.f, ms1 = 0.f, ms2 = 0.f, ms3 = 0.f;

    float4 prev;
    int x;
    if (xh == 0) {
        // x = 0: no x-diff, but y/z diffs apply.
        float4 s = g4[rowbase];
        if (yok) {
            float4 nb = g4[rowbase + XDIM * 4];
            float dx = nb.x - s.x, dy = nb.y - s.y, dz = nb.z - s.z, dw = nb.w - s.w;
            tv0 += fabsf(dx); tv1 += fabsf(dy); tv2 += fabsf(dz); tv3 += fabsf(dw);
            ms0 += dx * dx;   ms1 += dy * dy;   ms2 += dz * dz;   ms3 += dw * dw;
        }
        if (zok) {
            float4 nb = g4[rowbase + XDIM * XDIM * 4];
            float dx = nb.x - s.x, dy = nb.y - s.y, dz = nb.z - s.z, dw = nb.w - s.w;
            tv0 += fabsf(dx); tv1 += fabsf(dy); tv2 += fabsf(dz); tv3 += fabsf(dw);
            ms0 += dx * dx;   ms1 += dy * dy;   ms2 += dz * dz;   ms3 += dw * dw;
        }
        prev = s;
        x = 1;
    } else {
        prev = g4[rowbase + (size_t)63 * 4];  // carry across the half boundary
        x = 64;
    }
    int xend = xh * 64 + 64;

#pragma unroll 4
    for (; x < xend; x++) {
        size_t i = rowbase + (size_t)x * 4;
        float4 s = g4[i];
        // x-diff with carried prev
        {
            float dx = s.x - prev.x, dy = s.y - prev.y, dz = s.z - prev.z, dw = s.w - prev.w;
            tv0 += fabsf(dx); tv1 += fabsf(dy); tv2 += fabsf(dz); tv3 += fabsf(dw);
            ms0 += dx * dx;   ms1 += dy * dy;   ms2 += dz * dz;   ms3 += dw * dw;
        }
        prev = s;
        if (yok) {
            float4 nb = g4[i + XDIM * 4];
            float dx = nb.x - s.x, dy = nb.y - s.y, dz = nb.z - s.z, dw = nb.w - s.w;
            tv0 += fabsf(dx); tv1 += fabsf(dy); tv2 += fabsf(dz); tv3 += fabsf(dw);
            ms0 += dx * dx;   ms1 += dy * dy;   ms2 += dz * dz;   ms3 += dw * dw;
        }
        if (zok) {
            float4 nb = g4[i + XDIM * XDIM * 4];
            float dx = nb.x - s.x, dy = nb.y - s.y, dz = nb.z - s.z, dw = nb.w - s.w;
            tv0 += fabsf(dx); tv1 += fabsf(dy); tv2 += fabsf(dz); tv3 += fabsf(dw);
            ms0 += dx * dx;   ms1 += dy * dy;   ms2 += dz * dz;   ms3 += dw * dw;
        }
    }

    // Warp reduce over the 8 lanes sharing bg (xor lane bits 4,3,2).
#pragma unroll
    for (int off = 16; off >= 4; off >>= 1) {
        tv0 += __shfl_xor_sync(0xffffffffu, tv0, off);
        tv1 += __shfl_xor_sync(0xffffffffu, tv1, off);
        tv2 += __shfl_xor_sync(0xffffffffu, tv2, off);
        tv3 += __shfl_xor_sync(0xffffffffu, tv3, off);
        ms0 += __shfl_xor_sync(0xffffffffu, ms0, off);
        ms1 += __shfl_xor_sync(0xffffffffu, ms1, off);
        ms2 += __shfl_xor_sync(0xffffffffu, ms2, off);
        ms3 += __shfl_xor_sync(0xffffffffu, ms3, off);
    }

    __shared__ float s_tv[NB], s_mse[NB];
    if (threadIdx.x < NB) { s_tv[threadIdx.x] = 0.f; s_mse[threadIdx.x] = 0.f; }
    __syncthreads();

    if ((threadIdx.x & 31) < 4) {      // lane == bg for these lanes
        atomicAdd(&s_tv[bg * 4 + 0], tv0);
        atomicAdd(&s_tv[bg * 4 + 1], tv1);
        atomicAdd(&s_tv[bg * 4 + 2], tv2);
        atomicAdd(&s_tv[bg * 4 + 3], tv3);
        atomicAdd(&s_mse[bg * 4 + 0], ms0);
        atomicAdd(&s_mse[bg * 4 + 1], ms1);
        atomicAdd(&s_mse[bg * 4 + 2], ms2);
        atomicAdd(&s_mse[bg * 4 + 3], ms3);
    }
    __syncthreads();

    if (threadIdx.x < NB) {
        atomicAdd(&g_acc[threadIdx.x],      (double)s_tv[threadIdx.x]);
        atomicAdd(&g_acc[NB + threadIdx.x], (double)s_mse[threadIdx.x]);
    }
}

// ---------------------------------------------------------------------------
// Finalize: normalize, emit [2, B], and reset accumulators for the next replay.
// ---------------------------------------------------------------------------
__global__ void finalize_kernel(float* __restrict__ out) {
    int t = threadIdx.x;            // 0..31
    double norm = (t < NB) ? (double)X3 : (double)(2 * XDIM * XDIM - 2 * XDIM);
    out[t] = (float)(g_acc[t] / norm);
    g_acc[t] = 0.0;                 // restore invariant for next launch
}

extern "C" void kernel_launch(void* const* d_in, const int* in_sizes, int n_in,
                              void* d_out, int out_size) {
    const int*   indices = (const int*)d_in[0];
    const float* values  = (const float*)d_in[1];
    int N = in_sizes[0] / 3;        // 500000

    scatter_kernel<<<(N + 255) / 256, 256>>>(indices, values, N);

    dim3 rgrid(2, 8, 32);           // x-halves, y-tiles(16), z-tiles(4)
    reduce_kernel<<<rgrid, 256>>>();

    zero_touched_kernel<<<(N + 255) / 256, 256>>>(indices, N);
    finalize_kernel<<<1, 32>>>((float*)d_out);
}